// round 1
// baseline (speedup 1.0000x reference)
#include <cuda_runtime.h>
#include <math.h>

#define NN 100000
#define EE 1600000
#define ENN (EE + NN)
#define NB_BN 391      /* ceil(NN/256) */
#define NB_LOSS 12500  /* NN warps / 8 warps-per-block */
#define NB_SCAN 98     /* ceil(NN/1024) */
#define GX 782         /* ceil(NN/128) */

// ---------------- static scratch (no runtime allocation allowed) ----------------
__device__ float g_h0[NN * 128];
__device__ float g_h1[NN * 128];
__device__ float g_teach0[NN * 128];
__device__ float g_teach1[NN * 128];
__device__ float g_pred0[NN * 128];
__device__ float g_pred1[NN * 128];
__device__ float g_q[(size_t)NN * 512];

__device__ int   g_cnt[2 * NN];
__device__ float g_dinv[2 * NN];
__device__ int   g_rowptr[2 * (NN + 1)];
__device__ int   g_cursor[2 * NN];
__device__ int   g_col[2 * ENN];
__device__ float g_wgt[2 * ENN];
__device__ int   g_scan_incl[NN];
__device__ int   g_scan_bsum[NB_SCAN];

__device__ float g_psum[NB_BN * 128];
__device__ float g_psq[NB_BN * 128];
__device__ float g_scale[128];
__device__ float g_shift[128];
__device__ float g_losspart[NB_LOSS];

// ---------------- CSR build ----------------
__global__ void k_init_cnt(int* cnt) {
    int i = blockIdx.x * 256 + threadIdx.x;
    if (i < NN) cnt[i] = 1;  // self loop
}

__global__ void k_count(const int* __restrict__ ei, int* cnt) {
    int e = blockIdx.x * 256 + threadIdx.x;
    if (e < EE) atomicAdd(&cnt[ei[EE + e]], 1);  // dst = row 1
}

__global__ void k_dinv(const int* __restrict__ cnt, float* dinv) {
    int i = blockIdx.x * 256 + threadIdx.x;
    if (i < NN) dinv[i] = rsqrtf((float)cnt[i]);
}

__global__ void k_scan_block(const int* __restrict__ cnt, int* incl, int* bsum) {
    __shared__ int sm[1024];
    int i = blockIdx.x * 1024 + threadIdx.x;
    int v = (i < NN) ? cnt[i] : 0;
    sm[threadIdx.x] = v;
    __syncthreads();
    for (int off = 1; off < 1024; off <<= 1) {
        int t = (threadIdx.x >= off) ? sm[threadIdx.x - off] : 0;
        __syncthreads();
        sm[threadIdx.x] += t;
        __syncthreads();
    }
    if (i < NN) incl[i] = sm[threadIdx.x];
    if (threadIdx.x == 1023) bsum[blockIdx.x] = sm[1023];
}

__global__ void k_scan_sums(int* bsum) {
    if (threadIdx.x == 0 && blockIdx.x == 0) {
        int acc = 0;
        for (int b = 0; b < NB_SCAN; b++) { int t = bsum[b]; bsum[b] = acc; acc += t; }
    }
}

__global__ void k_finalize_rowptr(const int* __restrict__ cnt, const int* __restrict__ incl,
                                  const int* __restrict__ bsum, int* rowptr, int* cursor) {
    int i = blockIdx.x * 256 + threadIdx.x;
    if (i < NN) {
        int inclg = incl[i] + bsum[i >> 10];
        int excl = inclg - cnt[i];
        rowptr[i] = excl;
        cursor[i] = excl;
        if (i == NN - 1) rowptr[NN] = inclg;
    }
}

__global__ void k_fill(const int* __restrict__ ei, const float* __restrict__ dinv,
                       int* cursor, int* col, float* wgt) {
    int t = blockIdx.x * 256 + threadIdx.x;
    if (t < EE) {
        int s = ei[t], d = ei[EE + t];
        int p = atomicAdd(&cursor[d], 1);
        col[p] = s;
        wgt[p] = dinv[s] * dinv[d];
    } else if (t < ENN) {
        int i = t - EE;
        int p = atomicAdd(&cursor[i], 1);
        col[p] = i;
        wgt[p] = dinv[i] * dinv[i];
    }
}

// ---------------- propagate: one warp per dst row, 128-wide gather ----------------
__global__ __launch_bounds__(256) void k_prop(const int* __restrict__ rowptr,
                                              const int* __restrict__ col,
                                              const float* __restrict__ wgt,
                                              const float* __restrict__ h,
                                              const float* __restrict__ bias,
                                              float* __restrict__ out) {
    int w = (blockIdx.x * 256 + threadIdx.x) >> 5;
    int lane = threadIdx.x & 31;
    if (w >= NN) return;
    int beg = rowptr[w], end = rowptr[w + 1];
    float4 acc = make_float4(0.f, 0.f, 0.f, 0.f);
    const float4* H = (const float4*)h;
    for (int e = beg; e < end; e++) {
        int s = __ldg(&col[e]);
        float wv = __ldg(&wgt[e]);
        float4 v = __ldg(&H[(size_t)s * 32 + lane]);
        acc.x = fmaf(wv, v.x, acc.x);
        acc.y = fmaf(wv, v.y, acc.y);
        acc.z = fmaf(wv, v.z, acc.z);
        acc.w = fmaf(wv, v.w, acc.w);
    }
    float4 b = ((const float4*)bias)[lane];
    acc.x += b.x; acc.y += b.y; acc.z += b.z; acc.w += b.w;
    ((float4*)out)[(size_t)w * 32 + lane] = acc;
}

// ---------------- BN: deterministic two-stage stats ----------------
__global__ __launch_bounds__(256) void k_bn_stats(const float* __restrict__ x,
                                                  float* __restrict__ psum,
                                                  float* __restrict__ psq) {
    __shared__ float4 smS[256], smQ[256];
    int t = threadIdx.x;
    int cg = t & 31, rr = t >> 5;
    int rowStart = blockIdx.x * 256;
    int rowEnd = rowStart + 256; if (rowEnd > NN) rowEnd = NN;
    float4 s = make_float4(0.f, 0.f, 0.f, 0.f), q = s;
    const float4* X = (const float4*)x;
    for (int r = rowStart + rr; r < rowEnd; r += 8) {
        float4 v = X[(size_t)r * 32 + cg];
        s.x += v.x; s.y += v.y; s.z += v.z; s.w += v.w;
        q.x = fmaf(v.x, v.x, q.x); q.y = fmaf(v.y, v.y, q.y);
        q.z = fmaf(v.z, v.z, q.z); q.w = fmaf(v.w, v.w, q.w);
    }
    smS[t] = s; smQ[t] = q;
    __syncthreads();
    if (rr == 0) {
        for (int k = 1; k < 8; k++) {
            float4 a = smS[k * 32 + cg], b = smQ[k * 32 + cg];
            s.x += a.x; s.y += a.y; s.z += a.z; s.w += a.w;
            q.x += b.x; q.y += b.y; q.z += b.z; q.w += b.w;
        }
        ((float4*)psum)[blockIdx.x * 32 + cg] = s;
        ((float4*)psq)[blockIdx.x * 32 + cg] = q;
    }
}

__global__ void k_bn_fin(const float* __restrict__ psum, const float* __restrict__ psq,
                         const float* __restrict__ g, const float* __restrict__ be,
                         float* scale, float* shift) {
    int c = threadIdx.x;  // 128 threads
    float s = 0.f, q = 0.f;
    for (int b = 0; b < NB_BN; b++) { s += psum[b * 128 + c]; q += psq[b * 128 + c]; }
    float mu = s / (float)NN;
    float var = q / (float)NN - mu * mu;
    var = fmaxf(var, 0.f);
    float inv = rsqrtf(var + 1e-5f);
    float sc = g[c] * inv;
    scale[c] = sc;
    shift[c] = be[c] - mu * sc;
}

__global__ __launch_bounds__(256) void k_bn_apply(const float* __restrict__ x,
                                                  const float* __restrict__ scale,
                                                  const float* __restrict__ shift,
                                                  const float* __restrict__ aptr,
                                                  float* __restrict__ out) {
    int i = blockIdx.x * 256 + threadIdx.x;  // over NN*32 float4
    if (i >= NN * 32) return;
    int cg = i & 31;
    float a = *aptr;
    float4 v = ((const float4*)x)[i];
    float4 sc = ((const float4*)scale)[cg];
    float4 sh = ((const float4*)shift)[cg];
    v.x = fmaf(v.x, sc.x, sh.x); v.y = fmaf(v.y, sc.y, sh.y);
    v.z = fmaf(v.z, sc.z, sh.z); v.w = fmaf(v.w, sc.w, sh.w);
    v.x = v.x >= 0.f ? v.x : a * v.x;
    v.y = v.y >= 0.f ? v.y : a * v.y;
    v.z = v.z >= 0.f ? v.z : a * v.z;
    v.w = v.w >= 0.f ? v.w : a * v.w;
    ((float4*)out)[i] = v;
}

// ---------------- SGEMM: C[n,M] = A[n,K] @ B[K,M] (+bias, +prelu) ----------------
__global__ __launch_bounds__(256) void k_sgemm(const float* __restrict__ A,
                                               const float* __restrict__ B,
                                               const float* __restrict__ bias,
                                               const float* __restrict__ aprelu,
                                               float* __restrict__ C,
                                               int n, int K, int M) {
    __shared__ float As[16][128];
    __shared__ float Bs[16][128];
    const int bm = blockIdx.x * 128;
    const int bn = blockIdx.y * 128;
    const int tid = threadIdx.x;
    const int tx = tid & 15, ty = tid >> 4;
    const int rowBase = ty * 8, colBase = tx * 8;
    const int arow = tid >> 2, acol = (tid & 3) * 4;
    const int brow = tid >> 5, bcol = (tid & 31) * 4;

    float acc[8][8];
#pragma unroll
    for (int i = 0; i < 8; i++)
#pragma unroll
        for (int j = 0; j < 8; j++) acc[i][j] = 0.f;

    for (int k0 = 0; k0 < K; k0 += 16) {
#pragma unroll
        for (int i = 0; i < 2; i++) {
            int r = arow + i * 64;
            int gr = bm + r;
            float4 v = make_float4(0.f, 0.f, 0.f, 0.f);
            if (gr < n) v = *(const float4*)(A + (size_t)gr * K + k0 + acol);
            As[acol + 0][r] = v.x; As[acol + 1][r] = v.y;
            As[acol + 2][r] = v.z; As[acol + 3][r] = v.w;
        }
#pragma unroll
        for (int i = 0; i < 2; i++) {
            int r = brow + i * 8;
            float4 v = *(const float4*)(B + (size_t)(k0 + r) * M + bn + bcol);
            *(float4*)&Bs[r][bcol] = v;
        }
        __syncthreads();
#pragma unroll
        for (int k = 0; k < 16; k++) {
            float a[8], b[8];
#pragma unroll
            for (int i = 0; i < 8; i++) a[i] = As[k][rowBase + i];
#pragma unroll
            for (int j = 0; j < 8; j++) b[j] = Bs[k][colBase + j];
#pragma unroll
            for (int i = 0; i < 8; i++)
#pragma unroll
                for (int j = 0; j < 8; j++) acc[i][j] = fmaf(a[i], b[j], acc[i][j]);
        }
        __syncthreads();
    }

    float al = aprelu ? *aprelu : 0.f;
#pragma unroll
    for (int i = 0; i < 8; i++) {
        int gr = bm + rowBase + i;
        if (gr >= n) continue;
#pragma unroll
        for (int j = 0; j < 8; j += 4) {
            int gc = bn + colBase + j;
            float4 v = make_float4(acc[i][j], acc[i][j + 1], acc[i][j + 2], acc[i][j + 3]);
            if (bias) {
                float4 bb = *(const float4*)(bias + gc);
                v.x += bb.x; v.y += bb.y; v.z += bb.z; v.w += bb.w;
            }
            if (aprelu) {
                v.x = v.x >= 0.f ? v.x : al * v.x;
                v.y = v.y >= 0.f ? v.y : al * v.y;
                v.z = v.z >= 0.f ? v.z : al * v.z;
                v.w = v.w >= 0.f ? v.w : al * v.w;
            }
            *(float4*)(C + (size_t)gr * M + gc) = v;
        }
    }
}

// ---------------- loss ----------------
__global__ __launch_bounds__(256) void k_loss(const float4* __restrict__ p1,
                                              const float4* __restrict__ t2,
                                              const float4* __restrict__ p2,
                                              const float4* __restrict__ t1,
                                              float* __restrict__ part) {
    int w = (blockIdx.x * 256 + threadIdx.x) >> 5;
    int lane = threadIdx.x & 31;
    float contrib = 0.f;
    if (w < NN) {
        float4 a = p1[(size_t)w * 32 + lane];
        float4 b = t2[(size_t)w * 32 + lane];
        float4 c = p2[(size_t)w * 32 + lane];
        float4 d = t1[(size_t)w * 32 + lane];
        float dab = a.x * b.x + a.y * b.y + a.z * b.z + a.w * b.w;
        float naa = a.x * a.x + a.y * a.y + a.z * a.z + a.w * a.w;
        float nbb = b.x * b.x + b.y * b.y + b.z * b.z + b.w * b.w;
        float dcd = c.x * d.x + c.y * d.y + c.z * d.z + c.w * d.w;
        float ncc = c.x * c.x + c.y * c.y + c.z * c.z + c.w * c.w;
        float ndd = d.x * d.x + d.y * d.y + d.z * d.z + d.w * d.w;
        for (int off = 16; off; off >>= 1) {
            dab += __shfl_xor_sync(0xffffffffu, dab, off);
            naa += __shfl_xor_sync(0xffffffffu, naa, off);
            nbb += __shfl_xor_sync(0xffffffffu, nbb, off);
            dcd += __shfl_xor_sync(0xffffffffu, dcd, off);
            ncc += __shfl_xor_sync(0xffffffffu, ncc, off);
            ndd += __shfl_xor_sync(0xffffffffu, ndd, off);
        }
        if (lane == 0) {
            float c1 = dab / (fmaxf(sqrtf(naa), 1e-12f) * fmaxf(sqrtf(nbb), 1e-12f));
            float c2 = dcd / (fmaxf(sqrtf(ncc), 1e-12f) * fmaxf(sqrtf(ndd), 1e-12f));
            contrib = 4.f - 2.f * c1 - 2.f * c2;
        }
    }
    __shared__ float sm[8];
    int wl = threadIdx.x >> 5;
    if (lane == 0) sm[wl] = contrib;
    __syncthreads();
    if (threadIdx.x == 0) {
        float s = 0.f;
        for (int i = 0; i < 8; i++) s += sm[i];
        part[blockIdx.x] = s;
    }
}

__global__ void k_loss_fin(const float* __restrict__ part, float* __restrict__ outp) {
    __shared__ float sm[256];
    float s = 0.f;
    for (int i = threadIdx.x; i < NB_LOSS; i += 256) s += part[i];
    sm[threadIdx.x] = s;
    __syncthreads();
    for (int off = 128; off; off >>= 1) {
        if (threadIdx.x < off) sm[threadIdx.x] += sm[threadIdx.x + off];
        __syncthreads();
    }
    if (threadIdx.x == 0) outp[0] = sm[0] / (float)NN;
}

// ---------------- host orchestration ----------------
extern "C" void kernel_launch(void* const* d_in, const int* in_sizes, int n_in,
                              void* d_out, int out_size) {
    (void)in_sizes; (void)n_in; (void)out_size;
    const float* x1 = (const float*)d_in[0];
    const float* x2 = (const float*)d_in[1];
    const int* ei1 = (const int*)d_in[2];
    const int* ei2 = (const int*)d_in[3];
    const float* sp[10]; for (int i = 0; i < 10; i++) sp[i] = (const float*)d_in[4 + i];
    const float* tp[10]; for (int i = 0; i < 10; i++) tp[i] = (const float*)d_in[14 + i];
    const float* pW1 = (const float*)d_in[24];
    const float* pb1 = (const float*)d_in[25];
    const float* pa  = (const float*)d_in[26];
    const float* pW2 = (const float*)d_in[27];
    const float* pb2 = (const float*)d_in[28];
    float* out = (float*)d_out;

    float *h0, *h1, *teach0, *teach1, *pred0, *pred1, *q;
    float *dinvB, *wgtB, *psum, *psq, *scale, *shift, *losspart;
    int *cntB, *rpB, *curB, *colB, *incl, *bsum;
    cudaGetSymbolAddress((void**)&h0, g_h0);
    cudaGetSymbolAddress((void**)&h1, g_h1);
    cudaGetSymbolAddress((void**)&teach0, g_teach0);
    cudaGetSymbolAddress((void**)&teach1, g_teach1);
    cudaGetSymbolAddress((void**)&pred0, g_pred0);
    cudaGetSymbolAddress((void**)&pred1, g_pred1);
    cudaGetSymbolAddress((void**)&q, g_q);
    cudaGetSymbolAddress((void**)&cntB, g_cnt);
    cudaGetSymbolAddress((void**)&dinvB, g_dinv);
    cudaGetSymbolAddress((void**)&rpB, g_rowptr);
    cudaGetSymbolAddress((void**)&curB, g_cursor);
    cudaGetSymbolAddress((void**)&colB, g_col);
    cudaGetSymbolAddress((void**)&wgtB, g_wgt);
    cudaGetSymbolAddress((void**)&incl, g_scan_incl);
    cudaGetSymbolAddress((void**)&bsum, g_scan_bsum);
    cudaGetSymbolAddress((void**)&psum, g_psum);
    cudaGetSymbolAddress((void**)&psq, g_psq);
    cudaGetSymbolAddress((void**)&scale, g_scale);
    cudaGetSymbolAddress((void**)&shift, g_shift);
    cudaGetSymbolAddress((void**)&losspart, g_losspart);

    // --- build CSR for both views ---
    for (int v = 0; v < 2; v++) {
        const int* ei = v ? ei2 : ei1;
        int* cnt = cntB + v * NN;
        float* dinv = dinvB + v * NN;
        int* rp = rpB + v * (NN + 1);
        int* cur = curB + v * NN;
        int* col = colB + v * ENN;
        float* wgt = wgtB + v * ENN;
        k_init_cnt<<<NB_BN, 256>>>(cnt);
        k_count<<<(EE + 255) / 256, 256>>>(ei, cnt);
        k_dinv<<<NB_BN, 256>>>(cnt, dinv);
        k_scan_block<<<NB_SCAN, 1024>>>(cnt, incl, bsum);
        k_scan_sums<<<1, 32>>>(bsum);
        k_finalize_rowptr<<<NB_BN, 256>>>(cnt, incl, bsum, rp, cur);
        k_fill<<<(ENN + 255) / 256, 256>>>(ei, dinv, cur, col, wgt);
    }

    // --- 4 encoder runs ---
    auto encoder = [&](const float* x, int view, const float* const* P, float* outp) {
        const int* rp = rpB + view * (NN + 1);
        const int* col = colB + view * ENN;
        const float* wgt = wgtB + view * ENN;
        // layer 1
        k_sgemm<<<dim3(GX, 1), 256>>>(x, P[0], nullptr, nullptr, h0, NN, 256, 128);
        k_prop<<<12500, 256>>>(rp, col, wgt, h0, P[1], h1);
        k_bn_stats<<<NB_BN, 256>>>(h1, psum, psq);
        k_bn_fin<<<1, 128>>>(psum, psq, P[2], P[3], scale, shift);
        k_bn_apply<<<12500, 256>>>(h1, scale, shift, P[4], h1);
        // layer 2
        k_sgemm<<<dim3(GX, 1), 256>>>(h1, P[5], nullptr, nullptr, h0, NN, 128, 128);
        k_prop<<<12500, 256>>>(rp, col, wgt, h0, P[6], h1);
        k_bn_stats<<<NB_BN, 256>>>(h1, psum, psq);
        k_bn_fin<<<1, 128>>>(psum, psq, P[7], P[8], scale, shift);
        k_bn_apply<<<12500, 256>>>(h1, scale, shift, P[9], outp);
    };

    encoder(x1, 0, sp, out);                 // v1_student -> d_out[0 : NN*128)
    encoder(x2, 1, sp, out + (size_t)NN * 128);  // v2_student
    encoder(x1, 0, tp, teach0);              // v1_teacher
    encoder(x2, 1, tp, teach1);              // v2_teacher

    // --- predictor MLP on both student outputs ---
    k_sgemm<<<dim3(GX, 4), 256>>>(out, pW1, pb1, pa, q, NN, 128, 512);
    k_sgemm<<<dim3(GX, 1), 256>>>(q, pW2, pb2, nullptr, pred0, NN, 512, 128);
    k_sgemm<<<dim3(GX, 4), 256>>>(out + (size_t)NN * 128, pW1, pb1, pa, q, NN, 128, 512);
    k_sgemm<<<dim3(GX, 1), 256>>>(q, pW2, pb2, nullptr, pred1, NN, 512, 128);

    // --- loss ---
    k_loss<<<NB_LOSS, 256>>>((const float4*)pred0, (const float4*)teach1,
                             (const float4*)pred1, (const float4*)teach0, losspart);
    k_loss_fin<<<1, 256>>>(losspart, out + (size_t)2 * NN * 128);
}

// round 2
// speedup vs baseline: 1.0546x; 1.0546x over previous
#include <cuda_runtime.h>
#include <math.h>

#define NN 100000
#define EE 1600000
#define ENN (EE + NN)
#define NB_BN 391      /* ceil(NN/256) */
#define NB_LOSS 12500  /* NN warps / 8 warps-per-block */
#define NB_SCAN 98     /* ceil(NN/1024) */
#define GX 782         /* ceil(NN/128) */

// ---------------- static scratch (no runtime allocation allowed) ----------------
__device__ float g_h0[NN * 128];
__device__ float g_h1[NN * 128];
__device__ float g_teach0[NN * 128];
__device__ float g_teach1[NN * 128];
__device__ float g_pred0[NN * 128];
__device__ float g_pred1[NN * 128];
__device__ float g_q[(size_t)NN * 512];

__device__ int   g_cnt[2 * NN];
__device__ float g_dinv[2 * NN];
__device__ int   g_rowptr[2 * (NN + 1)];
__device__ int   g_cursor[2 * NN];
__device__ int   g_col[2 * ENN];
__device__ float g_wgt[2 * ENN];
__device__ int   g_scan_incl[NN];
__device__ int   g_scan_bsum[NB_SCAN];

__device__ float g_psum[NB_BN * 128];
__device__ float g_psq[NB_BN * 128];
__device__ float g_scale[128];
__device__ float g_shift[128];
__device__ float g_losspart[NB_LOSS];

// ---------------- CSR build ----------------
__global__ void k_init_cnt(int* cnt) {
    int i = blockIdx.x * 256 + threadIdx.x;
    if (i < NN) cnt[i] = 1;  // self loop
}

__global__ void k_count(const int* __restrict__ ei, int* cnt) {
    int e = blockIdx.x * 256 + threadIdx.x;
    if (e < EE) atomicAdd(&cnt[ei[EE + e]], 1);  // dst = row 1
}

__global__ void k_dinv(const int* __restrict__ cnt, float* dinv) {
    int i = blockIdx.x * 256 + threadIdx.x;
    if (i < NN) dinv[i] = rsqrtf((float)cnt[i]);
}

__global__ void k_scan_block(const int* __restrict__ cnt, int* incl, int* bsum) {
    __shared__ int sm[1024];
    int i = blockIdx.x * 1024 + threadIdx.x;
    int v = (i < NN) ? cnt[i] : 0;
    sm[threadIdx.x] = v;
    __syncthreads();
    for (int off = 1; off < 1024; off <<= 1) {
        int t = (threadIdx.x >= off) ? sm[threadIdx.x - off] : 0;
        __syncthreads();
        sm[threadIdx.x] += t;
        __syncthreads();
    }
    if (i < NN) incl[i] = sm[threadIdx.x];
    if (threadIdx.x == 1023) bsum[blockIdx.x] = sm[1023];
}

__global__ void k_scan_sums(int* bsum) {
    if (threadIdx.x == 0 && blockIdx.x == 0) {
        int acc = 0;
        for (int b = 0; b < NB_SCAN; b++) { int t = bsum[b]; bsum[b] = acc; acc += t; }
    }
}

__global__ void k_finalize_rowptr(const int* __restrict__ cnt, const int* __restrict__ incl,
                                  const int* __restrict__ bsum, int* rowptr, int* cursor) {
    int i = blockIdx.x * 256 + threadIdx.x;
    if (i < NN) {
        int inclg = incl[i] + bsum[i >> 10];
        int excl = inclg - cnt[i];
        rowptr[i] = excl;
        cursor[i] = excl;
        if (i == NN - 1) rowptr[NN] = inclg;
    }
}

__global__ void k_fill(const int* __restrict__ ei, const float* __restrict__ dinv,
                       int* cursor, int* col, float* wgt) {
    int t = blockIdx.x * 256 + threadIdx.x;
    if (t < EE) {
        int s = ei[t], d = ei[EE + t];
        int p = atomicAdd(&cursor[d], 1);
        col[p] = s;
        wgt[p] = dinv[s] * dinv[d];
    } else if (t < ENN) {
        int i = t - EE;
        int p = atomicAdd(&cursor[i], 1);
        col[p] = i;
        wgt[p] = dinv[i] * dinv[i];
    }
}

// ---------------- propagate: one warp per dst row, 128-wide gather ----------------
__global__ __launch_bounds__(256) void k_prop(const int* __restrict__ rowptr,
                                              const int* __restrict__ col,
                                              const float* __restrict__ wgt,
                                              const float* __restrict__ h,
                                              const float* __restrict__ bias,
                                              float* __restrict__ out) {
    int w = (blockIdx.x * 256 + threadIdx.x) >> 5;
    int lane = threadIdx.x & 31;
    if (w >= NN) return;
    int beg = rowptr[w], end = rowptr[w + 1];
    float4 acc = make_float4(0.f, 0.f, 0.f, 0.f);
    const float4* H = (const float4*)h;
    for (int e = beg; e < end; e++) {
        int s = __ldg(&col[e]);
        float wv = __ldg(&wgt[e]);
        float4 v = __ldg(&H[(size_t)s * 32 + lane]);
        acc.x = fmaf(wv, v.x, acc.x);
        acc.y = fmaf(wv, v.y, acc.y);
        acc.z = fmaf(wv, v.z, acc.z);
        acc.w = fmaf(wv, v.w, acc.w);
    }
    float4 b = ((const float4*)bias)[lane];
    acc.x += b.x; acc.y += b.y; acc.z += b.z; acc.w += b.w;
    ((float4*)out)[(size_t)w * 32 + lane] = acc;
}

// ---------------- BN: deterministic two-stage stats ----------------
__global__ __launch_bounds__(256) void k_bn_stats(const float* __restrict__ x,
                                                  float* __restrict__ psum,
                                                  float* __restrict__ psq) {
    __shared__ float4 smS[256], smQ[256];
    int t = threadIdx.x;
    int cg = t & 31, rr = t >> 5;
    int rowStart = blockIdx.x * 256;
    int rowEnd = rowStart + 256; if (rowEnd > NN) rowEnd = NN;
    float4 s = make_float4(0.f, 0.f, 0.f, 0.f), q = s;
    const float4* X = (const float4*)x;
    for (int r = rowStart + rr; r < rowEnd; r += 8) {
        float4 v = X[(size_t)r * 32 + cg];
        s.x += v.x; s.y += v.y; s.z += v.z; s.w += v.w;
        q.x = fmaf(v.x, v.x, q.x); q.y = fmaf(v.y, v.y, q.y);
        q.z = fmaf(v.z, v.z, q.z); q.w = fmaf(v.w, v.w, q.w);
    }
    smS[t] = s; smQ[t] = q;
    __syncthreads();
    if (rr == 0) {
        for (int k = 1; k < 8; k++) {
            float4 a = smS[k * 32 + cg], b = smQ[k * 32 + cg];
            s.x += a.x; s.y += a.y; s.z += a.z; s.w += a.w;
            q.x += b.x; q.y += b.y; q.z += b.z; q.w += b.w;
        }
        ((float4*)psum)[blockIdx.x * 32 + cg] = s;
        ((float4*)psq)[blockIdx.x * 32 + cg] = q;
    }
}

__global__ void k_bn_fin(const float* __restrict__ psum, const float* __restrict__ psq,
                         const float* __restrict__ g, const float* __restrict__ be,
                         float* scale, float* shift) {
    int c = threadIdx.x;  // 128 threads
    float s = 0.f, q = 0.f;
    for (int b = 0; b < NB_BN; b++) { s += psum[b * 128 + c]; q += psq[b * 128 + c]; }
    float mu = s / (float)NN;
    float var = q / (float)NN - mu * mu;
    var = fmaxf(var, 0.f);
    float inv = rsqrtf(var + 1e-5f);
    float sc = g[c] * inv;
    scale[c] = sc;
    shift[c] = be[c] - mu * sc;
}

__global__ __launch_bounds__(256) void k_bn_apply(const float* __restrict__ x,
                                                  const float* __restrict__ scale,
                                                  const float* __restrict__ shift,
                                                  const float* __restrict__ aptr,
                                                  float* __restrict__ out) {
    int i = blockIdx.x * 256 + threadIdx.x;  // over NN*32 float4
    if (i >= NN * 32) return;
    int cg = i & 31;
    float a = *aptr;
    float4 v = ((const float4*)x)[i];
    float4 sc = ((const float4*)scale)[cg];
    float4 sh = ((const float4*)shift)[cg];
    v.x = fmaf(v.x, sc.x, sh.x); v.y = fmaf(v.y, sc.y, sh.y);
    v.z = fmaf(v.z, sc.z, sh.z); v.w = fmaf(v.w, sc.w, sh.w);
    v.x = v.x >= 0.f ? v.x : a * v.x;
    v.y = v.y >= 0.f ? v.y : a * v.y;
    v.z = v.z >= 0.f ? v.z : a * v.z;
    v.w = v.w >= 0.f ? v.w : a * v.w;
    ((float4*)out)[i] = v;
}

// ---------------- SGEMM with packed fma.rn.f32x2 ----------------
// C[n,M] = A[n,K] @ B[K,M] (+bias, +prelu). 128x128 tile, 256 threads, 8x8/thread.
__global__ __launch_bounds__(256) void k_sgemm(const float* __restrict__ A,
                                               const float* __restrict__ B,
                                               const float* __restrict__ bias,
                                               const float* __restrict__ aprelu,
                                               float* __restrict__ C,
                                               int n, int K, int M) {
    __shared__ float As[16][128];
    __shared__ float Bs[16][128];
    const int bm = blockIdx.x * 128;
    const int bn = blockIdx.y * 128;
    const int tid = threadIdx.x;
    const int tx = tid & 15, ty = tid >> 4;
    const int rowBase = ty * 8, colBase = tx * 8;
    const int arow = tid >> 2, acol = (tid & 3) * 4;
    const int brow = tid >> 5, bcol = (tid & 31) * 4;

    // 8x8 fp32 accumulators held as 8x4 packed f32x2 pairs
    unsigned long long acc2[8][4];
#pragma unroll
    for (int i = 0; i < 8; i++)
#pragma unroll
        for (int j = 0; j < 4; j++) acc2[i][j] = 0ull;

    for (int k0 = 0; k0 < K; k0 += 16) {
#pragma unroll
        for (int i = 0; i < 2; i++) {
            int r = arow + i * 64;
            int gr = bm + r;
            float4 v = make_float4(0.f, 0.f, 0.f, 0.f);
            if (gr < n) v = *(const float4*)(A + (size_t)gr * K + k0 + acol);
            As[acol + 0][r] = v.x; As[acol + 1][r] = v.y;
            As[acol + 2][r] = v.z; As[acol + 3][r] = v.w;
        }
#pragma unroll
        for (int i = 0; i < 2; i++) {
            int r = brow + i * 8;
            float4 v = *(const float4*)(B + (size_t)(k0 + r) * M + bn + bcol);
            *(float4*)&Bs[r][bcol] = v;
        }
        __syncthreads();
#pragma unroll
        for (int k = 0; k < 16; k++) {
            unsigned long long a2[8], b2[4];
            const float* as = &As[k][rowBase];
#pragma unroll
            for (int i = 0; i < 8; i++) {
                float av = as[i];
                asm("mov.b64 %0, {%1, %1};" : "=l"(a2[i]) : "f"(av));
            }
            const unsigned long long* bs = (const unsigned long long*)&Bs[k][colBase];
#pragma unroll
            for (int j = 0; j < 4; j++) b2[j] = bs[j];
#pragma unroll
            for (int i = 0; i < 8; i++)
#pragma unroll
                for (int j = 0; j < 4; j++)
                    asm("fma.rn.f32x2 %0, %1, %2, %0;"
                        : "+l"(acc2[i][j]) : "l"(a2[i]), "l"(b2[j]));
        }
        __syncthreads();
    }

    float al = aprelu ? *aprelu : 0.f;
#pragma unroll
    for (int i = 0; i < 8; i++) {
        int gr = bm + rowBase + i;
        if (gr >= n) continue;
#pragma unroll
        for (int j = 0; j < 8; j += 4) {
            int gc = bn + colBase + j;
            float p0, p1, p2, p3;
            asm("mov.b64 {%0, %1}, %2;" : "=f"(p0), "=f"(p1) : "l"(acc2[i][j >> 1]));
            asm("mov.b64 {%0, %1}, %2;" : "=f"(p2), "=f"(p3) : "l"(acc2[i][(j >> 1) + 1]));
            float4 v = make_float4(p0, p1, p2, p3);
            if (bias) {
                float4 bb = *(const float4*)(bias + gc);
                v.x += bb.x; v.y += bb.y; v.z += bb.z; v.w += bb.w;
            }
            if (aprelu) {
                v.x = v.x >= 0.f ? v.x : al * v.x;
                v.y = v.y >= 0.f ? v.y : al * v.y;
                v.z = v.z >= 0.f ? v.z : al * v.z;
                v.w = v.w >= 0.f ? v.w : al * v.w;
            }
            *(float4*)(C + (size_t)gr * M + gc) = v;
        }
    }
}

// ---------------- loss ----------------
__global__ __launch_bounds__(256) void k_loss(const float4* __restrict__ p1,
                                              const float4* __restrict__ t2,
                                              const float4* __restrict__ p2,
                                              const float4* __restrict__ t1,
                                              float* __restrict__ part) {
    int w = (blockIdx.x * 256 + threadIdx.x) >> 5;
    int lane = threadIdx.x & 31;
    float contrib = 0.f;
    if (w < NN) {
        float4 a = p1[(size_t)w * 32 + lane];
        float4 b = t2[(size_t)w * 32 + lane];
        float4 c = p2[(size_t)w * 32 + lane];
        float4 d = t1[(size_t)w * 32 + lane];
        float dab = a.x * b.x + a.y * b.y + a.z * b.z + a.w * b.w;
        float naa = a.x * a.x + a.y * a.y + a.z * a.z + a.w * a.w;
        float nbb = b.x * b.x + b.y * b.y + b.z * b.z + b.w * b.w;
        float dcd = c.x * d.x + c.y * d.y + c.z * d.z + c.w * d.w;
        float ncc = c.x * c.x + c.y * c.y + c.z * c.z + c.w * c.w;
        float ndd = d.x * d.x + d.y * d.y + d.z * d.z + d.w * d.w;
        for (int off = 16; off; off >>= 1) {
            dab += __shfl_xor_sync(0xffffffffu, dab, off);
            naa += __shfl_xor_sync(0xffffffffu, naa, off);
            nbb += __shfl_xor_sync(0xffffffffu, nbb, off);
            dcd += __shfl_xor_sync(0xffffffffu, dcd, off);
            ncc += __shfl_xor_sync(0xffffffffu, ncc, off);
            ndd += __shfl_xor_sync(0xffffffffu, ndd, off);
        }
        if (lane == 0) {
            float c1 = dab / (fmaxf(sqrtf(naa), 1e-12f) * fmaxf(sqrtf(nbb), 1e-12f));
            float c2 = dcd / (fmaxf(sqrtf(ncc), 1e-12f) * fmaxf(sqrtf(ndd), 1e-12f));
            contrib = 4.f - 2.f * c1 - 2.f * c2;
        }
    }
    __shared__ float sm[8];
    int wl = threadIdx.x >> 5;
    if (lane == 0) sm[wl] = contrib;
    __syncthreads();
    if (threadIdx.x == 0) {
        float s = 0.f;
        for (int i = 0; i < 8; i++) s += sm[i];
        part[blockIdx.x] = s;
    }
}

__global__ void k_loss_fin(const float* __restrict__ part, float* __restrict__ outp) {
    __shared__ float sm[256];
    float s = 0.f;
    for (int i = threadIdx.x; i < NB_LOSS; i += 256) s += part[i];
    sm[threadIdx.x] = s;
    __syncthreads();
    for (int off = 128; off; off >>= 1) {
        if (threadIdx.x < off) sm[threadIdx.x] += sm[threadIdx.x + off];
        __syncthreads();
    }
    if (threadIdx.x == 0) outp[0] = sm[0] / (float)NN;
}

// ---------------- host orchestration ----------------
extern "C" void kernel_launch(void* const* d_in, const int* in_sizes, int n_in,
                              void* d_out, int out_size) {
    (void)in_sizes; (void)n_in; (void)out_size;
    const float* x1 = (const float*)d_in[0];
    const float* x2 = (const float*)d_in[1];
    const int* ei1 = (const int*)d_in[2];
    const int* ei2 = (const int*)d_in[3];
    const float* sp[10]; for (int i = 0; i < 10; i++) sp[i] = (const float*)d_in[4 + i];
    const float* tp[10]; for (int i = 0; i < 10; i++) tp[i] = (const float*)d_in[14 + i];
    const float* pW1 = (const float*)d_in[24];
    const float* pb1 = (const float*)d_in[25];
    const float* pa  = (const float*)d_in[26];
    const float* pW2 = (const float*)d_in[27];
    const float* pb2 = (const float*)d_in[28];
    float* out = (float*)d_out;

    float *h0, *h1, *teach0, *teach1, *pred0, *pred1, *q;
    float *dinvB, *wgtB, *psum, *psq, *scale, *shift, *losspart;
    int *cntB, *rpB, *curB, *colB, *incl, *bsum;
    cudaGetSymbolAddress((void**)&h0, g_h0);
    cudaGetSymbolAddress((void**)&h1, g_h1);
    cudaGetSymbolAddress((void**)&teach0, g_teach0);
    cudaGetSymbolAddress((void**)&teach1, g_teach1);
    cudaGetSymbolAddress((void**)&pred0, g_pred0);
    cudaGetSymbolAddress((void**)&pred1, g_pred1);
    cudaGetSymbolAddress((void**)&q, g_q);
    cudaGetSymbolAddress((void**)&cntB, g_cnt);
    cudaGetSymbolAddress((void**)&dinvB, g_dinv);
    cudaGetSymbolAddress((void**)&rpB, g_rowptr);
    cudaGetSymbolAddress((void**)&curB, g_cursor);
    cudaGetSymbolAddress((void**)&colB, g_col);
    cudaGetSymbolAddress((void**)&wgtB, g_wgt);
    cudaGetSymbolAddress((void**)&incl, g_scan_incl);
    cudaGetSymbolAddress((void**)&bsum, g_scan_bsum);
    cudaGetSymbolAddress((void**)&psum, g_psum);
    cudaGetSymbolAddress((void**)&psq, g_psq);
    cudaGetSymbolAddress((void**)&scale, g_scale);
    cudaGetSymbolAddress((void**)&shift, g_shift);
    cudaGetSymbolAddress((void**)&losspart, g_losspart);

    // --- build CSR for both views ---
    for (int v = 0; v < 2; v++) {
        const int* ei = v ? ei2 : ei1;
        int* cnt = cntB + v * NN;
        float* dinv = dinvB + v * NN;
        int* rp = rpB + v * (NN + 1);
        int* cur = curB + v * NN;
        int* col = colB + v * ENN;
        float* wgt = wgtB + v * ENN;
        k_init_cnt<<<NB_BN, 256>>>(cnt);
        k_count<<<(EE + 255) / 256, 256>>>(ei, cnt);
        k_dinv<<<NB_BN, 256>>>(cnt, dinv);
        k_scan_block<<<NB_SCAN, 1024>>>(cnt, incl, bsum);
        k_scan_sums<<<1, 32>>>(bsum);
        k_finalize_rowptr<<<NB_BN, 256>>>(cnt, incl, bsum, rp, cur);
        k_fill<<<(ENN + 255) / 256, 256>>>(ei, dinv, cur, col, wgt);
    }

    // --- 4 encoder runs ---
    auto encoder = [&](const float* x, int view, const float* const* P, float* outp) {
        const int* rp = rpB + view * (NN + 1);
        const int* col = colB + view * ENN;
        const float* wgt = wgtB + view * ENN;
        // layer 1
        k_sgemm<<<dim3(GX, 1), 256>>>(x, P[0], nullptr, nullptr, h0, NN, 256, 128);
        k_prop<<<12500, 256>>>(rp, col, wgt, h0, P[1], h1);
        k_bn_stats<<<NB_BN, 256>>>(h1, psum, psq);
        k_bn_fin<<<1, 128>>>(psum, psq, P[2], P[3], scale, shift);
        k_bn_apply<<<12500, 256>>>(h1, scale, shift, P[4], h1);
        // layer 2
        k_sgemm<<<dim3(GX, 1), 256>>>(h1, P[5], nullptr, nullptr, h0, NN, 128, 128);
        k_prop<<<12500, 256>>>(rp, col, wgt, h0, P[6], h1);
        k_bn_stats<<<NB_BN, 256>>>(h1, psum, psq);
        k_bn_fin<<<1, 128>>>(psum, psq, P[7], P[8], scale, shift);
        k_bn_apply<<<12500, 256>>>(h1, scale, shift, P[9], outp);
    };

    encoder(x1, 0, sp, out);                 // v1_student -> d_out[0 : NN*128)
    encoder(x2, 1, sp, out + (size_t)NN * 128);  // v2_student
    encoder(x1, 0, tp, teach0);              // v1_teacher
    encoder(x2, 1, tp, teach1);              // v2_teacher

    // --- predictor MLP on both student outputs ---
    k_sgemm<<<dim3(GX, 4), 256>>>(out, pW1, pb1, pa, q, NN, 128, 512);
    k_sgemm<<<dim3(GX, 1), 256>>>(q, pW2, pb2, nullptr, pred0, NN, 512, 128);
    k_sgemm<<<dim3(GX, 4), 256>>>(out + (size_t)NN * 128, pW1, pb1, pa, q, NN, 128, 512);
    k_sgemm<<<dim3(GX, 1), 256>>>(q, pW2, pb2, nullptr, pred1, NN, 512, 128);

    // --- loss ---
    k_loss<<<NB_LOSS, 256>>>((const float4*)pred0, (const float4*)teach1,
                             (const float4*)pred1, (const float4*)teach0, losspart);
    k_loss_fin<<<1, 256>>>(losspart, out + (size_t)2 * NN * 128);
}

// round 4
// speedup vs baseline: 1.0956x; 1.0389x over previous
#include <cuda_runtime.h>
#include <math.h>
#include <stdint.h>

#define NN 100000
#define EE 1600000
#define ENN (EE + NN)
#define NB_BN 391      /* ceil(NN/256) */
#define NB_LOSS 12500  /* NN warps / 8 warps-per-block */
#define NB_SCAN 98     /* ceil(NN/1024) */
#define GX 782         /* ceil(NN/128) */

// ---------------- static scratch ----------------
__device__ float g_h0[NN * 128];
__device__ float g_h1[NN * 128];
__device__ float g_teach0[NN * 128];
__device__ float g_teach1[NN * 128];
__device__ float g_pred0[NN * 128];
__device__ float g_pred1[NN * 128];
__device__ float g_q[(size_t)NN * 512];

__device__ int   g_cnt[2 * NN];
__device__ float g_dinv[2 * NN];
__device__ int   g_rowptr[2 * (NN + 1)];
__device__ int   g_cursor[2 * NN];
__device__ int   g_col[2 * ENN];
__device__ float g_wgt[2 * ENN];
__device__ int   g_scan_incl[NN];
__device__ int   g_scan_bsum[NB_SCAN];

__device__ float g_psum[NB_BN * 128];
__device__ float g_psq[NB_BN * 128];
__device__ float g_scale[128];
__device__ float g_shift[128];
__device__ float g_losspart[NB_LOSS];

// ---------------- tf32 helpers ----------------
__device__ __forceinline__ void tf32_split(float v, uint32_t& h, uint32_t& l) {
    uint32_t hv;
    asm("cvt.rna.tf32.f32 %0, %1;" : "=r"(hv) : "f"(v));
    float r = v - __uint_as_float(hv);
    uint32_t lv;
    asm("cvt.rna.tf32.f32 %0, %1;" : "=r"(lv) : "f"(r));
    h = hv; l = lv;
}

__device__ __forceinline__ void mma_tf32(float* c, const uint32_t* a, const uint32_t* b) {
    asm volatile(
        "mma.sync.aligned.m16n8k8.row.col.f32.tf32.tf32.f32 "
        "{%0,%1,%2,%3},{%4,%5,%6,%7},{%8,%9},{%0,%1,%2,%3};"
        : "+f"(c[0]), "+f"(c[1]), "+f"(c[2]), "+f"(c[3])
        : "r"(a[0]), "r"(a[1]), "r"(a[2]), "r"(a[3]), "r"(b[0]), "r"(b[1]));
}

// ---------------- tensor-core tf32-split GEMM ----------------
// C[n,Mt] = A[n,K] @ W[K,Mt] (+bias, +prelu). CTA tile 128x128, 8 warps (2m x 4n),
// warp tile 64x32. K chunked by 32 through padded SMEM (hi+lo split).
#define KC 32
#define AS_STR 36
#define BS_STR 132
#define DSMEM_TC ((2 * 128 * AS_STR + 2 * KC * BS_STR) * 4)

__global__ __launch_bounds__(256) void k_tc_gemm(
    const float* __restrict__ A, const float* __restrict__ W,
    const float* __restrict__ bias, const float* __restrict__ aprelu,
    float* __restrict__ C, int n, int K, int Mt) {
    extern __shared__ float smf[];
    float* Ah = smf;
    float* Al = smf + 128 * AS_STR;
    float* Bh = smf + 2 * 128 * AS_STR;
    float* Bl = Bh + KC * BS_STR;

    const int tid = threadIdx.x, lane = tid & 31, wid = tid >> 5;
    const int wm = wid & 1, wn = wid >> 1;
    const int bm = blockIdx.x * 128, bn = blockIdx.y * 128;
    const int lg = lane >> 2, lt = lane & 3;

    float acc[4][4][4];
#pragma unroll
    for (int i = 0; i < 4; i++)
#pragma unroll
        for (int j = 0; j < 4; j++)
#pragma unroll
            for (int k = 0; k < 4; k++) acc[i][j][k] = 0.f;

    const int arow = tid >> 1, aks = (tid & 1) * 16;
    const int bkr = tid >> 3, bns = (tid & 7) * 16;

    for (int k0 = 0; k0 < K; k0 += KC) {
        // stage A chunk [128][32] as hi/lo
        {
            int gr = bm + arow;
#pragma unroll
            for (int q = 0; q < 4; q++) {
                float4 v = make_float4(0.f, 0.f, 0.f, 0.f);
                if (gr < n) v = *(const float4*)(A + (size_t)gr * K + k0 + aks + q * 4);
                uint32_t h0_, l0_, h1_, l1_, h2_, l2_, h3_, l3_;
                tf32_split(v.x, h0_, l0_); tf32_split(v.y, h1_, l1_);
                tf32_split(v.z, h2_, l2_); tf32_split(v.w, h3_, l3_);
                int b = arow * AS_STR + aks + q * 4;
                Ah[b + 0] = __uint_as_float(h0_); Ah[b + 1] = __uint_as_float(h1_);
                Ah[b + 2] = __uint_as_float(h2_); Ah[b + 3] = __uint_as_float(h3_);
                Al[b + 0] = __uint_as_float(l0_); Al[b + 1] = __uint_as_float(l1_);
                Al[b + 2] = __uint_as_float(l2_); Al[b + 3] = __uint_as_float(l3_);
            }
        }
        // stage B chunk [32][128] as hi/lo (W is [K,Mt] row-major: direct)
        {
#pragma unroll
            for (int q = 0; q < 4; q++) {
                float4 v = *(const float4*)(W + (size_t)(k0 + bkr) * Mt + bn + bns + q * 4);
                uint32_t h0_, l0_, h1_, l1_, h2_, l2_, h3_, l3_;
                tf32_split(v.x, h0_, l0_); tf32_split(v.y, h1_, l1_);
                tf32_split(v.z, h2_, l2_); tf32_split(v.w, h3_, l3_);
                int b = bkr * BS_STR + bns + q * 4;
                Bh[b + 0] = __uint_as_float(h0_); Bh[b + 1] = __uint_as_float(h1_);
                Bh[b + 2] = __uint_as_float(h2_); Bh[b + 3] = __uint_as_float(h3_);
                Bl[b + 0] = __uint_as_float(l0_); Bl[b + 1] = __uint_as_float(l1_);
                Bl[b + 2] = __uint_as_float(l2_); Bl[b + 3] = __uint_as_float(l3_);
            }
        }
        __syncthreads();
#pragma unroll
        for (int kk = 0; kk < KC; kk += 8) {
            uint32_t ah[4][4], al[4][4], bh[4][2], bl[4][2];
            const int ak = kk + lt;
            const int ar0 = wm * 64 + lg;
#pragma unroll
            for (int mf = 0; mf < 4; mf++) {
                int r = ar0 + mf * 16;
                ah[mf][0] = __float_as_uint(Ah[r * AS_STR + ak]);
                ah[mf][1] = __float_as_uint(Ah[(r + 8) * AS_STR + ak]);
                ah[mf][2] = __float_as_uint(Ah[r * AS_STR + ak + 4]);
                ah[mf][3] = __float_as_uint(Ah[(r + 8) * AS_STR + ak + 4]);
                al[mf][0] = __float_as_uint(Al[r * AS_STR + ak]);
                al[mf][1] = __float_as_uint(Al[(r + 8) * AS_STR + ak]);
                al[mf][2] = __float_as_uint(Al[r * AS_STR + ak + 4]);
                al[mf][3] = __float_as_uint(Al[(r + 8) * AS_STR + ak + 4]);
            }
            const int bk = kk + lt;
            const int bn0 = wn * 32 + lg;
#pragma unroll
            for (int nf = 0; nf < 4; nf++) {
                int c = bn0 + nf * 8;
                bh[nf][0] = __float_as_uint(Bh[bk * BS_STR + c]);
                bh[nf][1] = __float_as_uint(Bh[(bk + 4) * BS_STR + c]);
                bl[nf][0] = __float_as_uint(Bl[bk * BS_STR + c]);
                bl[nf][1] = __float_as_uint(Bl[(bk + 4) * BS_STR + c]);
            }
#pragma unroll
            for (int mf = 0; mf < 4; mf++)
#pragma unroll
                for (int nf = 0; nf < 4; nf++) {
                    mma_tf32(acc[mf][nf], ah[mf], bh[nf]);
                    mma_tf32(acc[mf][nf], ah[mf], bl[nf]);
                    mma_tf32(acc[mf][nf], al[mf], bh[nf]);
                }
        }
        __syncthreads();
    }

    // epilogue
    float alv = aprelu ? __ldg(aprelu) : 0.f;
#pragma unroll
    for (int mf = 0; mf < 4; mf++) {
        int r0 = bm + wm * 64 + mf * 16 + lg;
#pragma unroll
        for (int nf = 0; nf < 4; nf++) {
            int gc = bn + wn * 32 + nf * 8 + lt * 2;
            float2 v0 = make_float2(acc[mf][nf][0], acc[mf][nf][1]);
            float2 v1 = make_float2(acc[mf][nf][2], acc[mf][nf][3]);
            if (bias) {
                float b0 = __ldg(&bias[gc]), b1 = __ldg(&bias[gc + 1]);
                v0.x += b0; v0.y += b1; v1.x += b0; v1.y += b1;
            }
            if (aprelu) {
                v0.x = v0.x >= 0.f ? v0.x : alv * v0.x;
                v0.y = v0.y >= 0.f ? v0.y : alv * v0.y;
                v1.x = v1.x >= 0.f ? v1.x : alv * v1.x;
                v1.y = v1.y >= 0.f ? v1.y : alv * v1.y;
            }
            if (r0 < n) *(float2*)(C + (size_t)r0 * Mt + gc) = v0;
            if (r0 + 8 < n) *(float2*)(C + (size_t)(r0 + 8) * Mt + gc) = v1;
        }
    }
}

// ---------------- CSR build ----------------
__global__ void k_init_cnt(int* cnt) {
    int i = blockIdx.x * 256 + threadIdx.x;
    if (i < NN) cnt[i] = 1;
}
__global__ void k_count(const int* __restrict__ ei, int* cnt) {
    int e = blockIdx.x * 256 + threadIdx.x;
    if (e < EE) atomicAdd(&cnt[ei[EE + e]], 1);
}
__global__ void k_dinv(const int* __restrict__ cnt, float* dinv) {
    int i = blockIdx.x * 256 + threadIdx.x;
    if (i < NN) dinv[i] = rsqrtf((float)cnt[i]);
}
__global__ void k_scan_block(const int* __restrict__ cnt, int* incl, int* bsum) {
    __shared__ int sm[1024];
    int i = blockIdx.x * 1024 + threadIdx.x;
    int v = (i < NN) ? cnt[i] : 0;
    sm[threadIdx.x] = v;
    __syncthreads();
    for (int off = 1; off < 1024; off <<= 1) {
        int t = (threadIdx.x >= off) ? sm[threadIdx.x - off] : 0;
        __syncthreads();
        sm[threadIdx.x] += t;
        __syncthreads();
    }
    if (i < NN) incl[i] = sm[threadIdx.x];
    if (threadIdx.x == 1023) bsum[blockIdx.x] = sm[1023];
}
__global__ void k_scan_sums(int* bsum) {
    if (threadIdx.x == 0 && blockIdx.x == 0) {
        int acc = 0;
        for (int b = 0; b < NB_SCAN; b++) { int t = bsum[b]; bsum[b] = acc; acc += t; }
    }
}
__global__ void k_finalize_rowptr(const int* __restrict__ cnt, const int* __restrict__ incl,
                                  const int* __restrict__ bsum, int* rowptr, int* cursor) {
    int i = blockIdx.x * 256 + threadIdx.x;
    if (i < NN) {
        int inclg = incl[i] + bsum[i >> 10];
        int excl = inclg - cnt[i];
        rowptr[i] = excl;
        cursor[i] = excl;
        if (i == NN - 1) rowptr[NN] = inclg;
    }
}
__global__ void k_fill(const int* __restrict__ ei, const float* __restrict__ dinv,
                       int* cursor, int* col, float* wgt) {
    int t = blockIdx.x * 256 + threadIdx.x;
    if (t < EE) {
        int s = ei[t], d = ei[EE + t];
        int p = atomicAdd(&cursor[d], 1);
        col[p] = s;
        wgt[p] = dinv[s] * dinv[d];
    } else if (t < ENN) {
        int i = t - EE;
        int p = atomicAdd(&cursor[i], 1);
        col[p] = i;
        wgt[p] = dinv[i] * dinv[i];
    }
}

// ---------------- propagate ----------------
__global__ __launch_bounds__(256) void k_prop(const int* __restrict__ rowptr,
                                              const int* __restrict__ col,
                                              const float* __restrict__ wgt,
                                              const float* __restrict__ h,
                                              const float* __restrict__ bias,
                                              float* __restrict__ out) {
    int w = (blockIdx.x * 256 + threadIdx.x) >> 5;
    int lane = threadIdx.x & 31;
    if (w >= NN) return;
    int beg = rowptr[w], end = rowptr[w + 1];
    float4 acc = make_float4(0.f, 0.f, 0.f, 0.f);
    const float4* H = (const float4*)h;
    for (int e = beg; e < end; e++) {
        int s = __ldg(&col[e]);
        float wv = __ldg(&wgt[e]);
        float4 v = __ldg(&H[(size_t)s * 32 + lane]);
        acc.x = fmaf(wv, v.x, acc.x);
        acc.y = fmaf(wv, v.y, acc.y);
        acc.z = fmaf(wv, v.z, acc.z);
        acc.w = fmaf(wv, v.w, acc.w);
    }
    float4 b = ((const float4*)bias)[lane];
    acc.x += b.x; acc.y += b.y; acc.z += b.z; acc.w += b.w;
    ((float4*)out)[(size_t)w * 32 + lane] = acc;
}

// ---------------- BN ----------------
__global__ __launch_bounds__(256) void k_bn_stats(const float* __restrict__ x,
                                                  float* __restrict__ psum,
                                                  float* __restrict__ psq) {
    __shared__ float4 smS[256], smQ[256];
    int t = threadIdx.x;
    int cg = t & 31, rr = t >> 5;
    int rowStart = blockIdx.x * 256;
    int rowEnd = rowStart + 256; if (rowEnd > NN) rowEnd = NN;
    float4 s = make_float4(0.f, 0.f, 0.f, 0.f), q = s;
    const float4* X = (const float4*)x;
    for (int r = rowStart + rr; r < rowEnd; r += 8) {
        float4 v = X[(size_t)r * 32 + cg];
        s.x += v.x; s.y += v.y; s.z += v.z; s.w += v.w;
        q.x = fmaf(v.x, v.x, q.x); q.y = fmaf(v.y, v.y, q.y);
        q.z = fmaf(v.z, v.z, q.z); q.w = fmaf(v.w, v.w, q.w);
    }
    smS[t] = s; smQ[t] = q;
    __syncthreads();
    if (rr == 0) {
        for (int k = 1; k < 8; k++) {
            float4 a = smS[k * 32 + cg], b = smQ[k * 32 + cg];
            s.x += a.x; s.y += a.y; s.z += a.z; s.w += a.w;
            q.x += b.x; q.y += b.y; q.z += b.z; q.w += b.w;
        }
        ((float4*)psum)[blockIdx.x * 32 + cg] = s;
        ((float4*)psq)[blockIdx.x * 32 + cg] = q;
    }
}
__global__ void k_bn_fin(const float* __restrict__ psum, const float* __restrict__ psq,
                         const float* __restrict__ g, const float* __restrict__ be,
                         float* scale, float* shift) {
    int c = threadIdx.x;
    float s = 0.f, q = 0.f;
    for (int b = 0; b < NB_BN; b++) { s += psum[b * 128 + c]; q += psq[b * 128 + c]; }
    float mu = s / (float)NN;
    float var = q / (float)NN - mu * mu;
    var = fmaxf(var, 0.f);
    float inv = rsqrtf(var + 1e-5f);
    float sc = g[c] * inv;
    scale[c] = sc;
    shift[c] = be[c] - mu * sc;
}
__global__ __launch_bounds__(256) void k_bn_apply(const float* __restrict__ x,
                                                  const float* __restrict__ scale,
                                                  const float* __restrict__ shift,
                                                  const float* __restrict__ aptr,
                                                  float* __restrict__ out) {
    int i = blockIdx.x * 256 + threadIdx.x;
    if (i >= NN * 32) return;
    int cg = i & 31;
    float a = *aptr;
    float4 v = ((const float4*)x)[i];
    float4 sc = ((const float4*)scale)[cg];
    float4 sh = ((const float4*)shift)[cg];
    v.x = fmaf(v.x, sc.x, sh.x); v.y = fmaf(v.y, sc.y, sh.y);
    v.z = fmaf(v.z, sc.z, sh.z); v.w = fmaf(v.w, sc.w, sh.w);
    v.x = v.x >= 0.f ? v.x : a * v.x;
    v.y = v.y >= 0.f ? v.y : a * v.y;
    v.z = v.z >= 0.f ? v.z : a * v.z;
    v.w = v.w >= 0.f ? v.w : a * v.w;
    ((float4*)out)[i] = v;
}

// ---------------- loss ----------------
__global__ __launch_bounds__(256) void k_loss(const float4* __restrict__ p1,
                                              const float4* __restrict__ t2,
                                              const float4* __restrict__ p2,
                                              const float4* __restrict__ t1,
                                              float* __restrict__ part) {
    int w = (blockIdx.x * 256 + threadIdx.x) >> 5;
    int lane = threadIdx.x & 31;
    float contrib = 0.f;
    if (w < NN) {
        float4 a = p1[(size_t)w * 32 + lane];
        float4 b = t2[(size_t)w * 32 + lane];
        float4 c = p2[(size_t)w * 32 + lane];
        float4 d = t1[(size_t)w * 32 + lane];
        float dab = a.x * b.x + a.y * b.y + a.z * b.z + a.w * b.w;
        float naa = a.x * a.x + a.y * a.y + a.z * a.z + a.w * a.w;
        float nbb = b.x * b.x + b.y * b.y + b.z * b.z + b.w * b.w;
        float dcd = c.x * d.x + c.y * d.y + c.z * d.z + c.w * d.w;
        float ncc = c.x * c.x + c.y * c.y + c.z * c.z + c.w * c.w;
        float ndd = d.x * d.x + d.y * d.y + d.z * d.z + d.w * d.w;
        for (int off = 16; off; off >>= 1) {
            dab += __shfl_xor_sync(0xffffffffu, dab, off);
            naa += __shfl_xor_sync(0xffffffffu, naa, off);
            nbb += __shfl_xor_sync(0xffffffffu, nbb, off);
            dcd += __shfl_xor_sync(0xffffffffu, dcd, off);
            ncc += __shfl_xor_sync(0xffffffffu, ncc, off);
            ndd += __shfl_xor_sync(0xffffffffu, ndd, off);
        }
        if (lane == 0) {
            float c1 = dab / (fmaxf(sqrtf(naa), 1e-12f) * fmaxf(sqrtf(nbb), 1e-12f));
            float c2 = dcd / (fmaxf(sqrtf(ncc), 1e-12f) * fmaxf(sqrtf(ndd), 1e-12f));
            contrib = 4.f - 2.f * c1 - 2.f * c2;
        }
    }
    __shared__ float sm[8];
    int wl = threadIdx.x >> 5;
    if (lane == 0) sm[wl] = contrib;
    __syncthreads();
    if (threadIdx.x == 0) {
        float s = 0.f;
        for (int i = 0; i < 8; i++) s += sm[i];
        part[blockIdx.x] = s;
    }
}
__global__ void k_loss_fin(const float* __restrict__ part, float* __restrict__ outp) {
    __shared__ float sm[256];
    float s = 0.f;
    for (int i = threadIdx.x; i < NB_LOSS; i += 256) s += part[i];
    sm[threadIdx.x] = s;
    __syncthreads();
    for (int off = 128; off; off >>= 1) {
        if (threadIdx.x < off) sm[threadIdx.x] += sm[threadIdx.x + off];
        __syncthreads();
    }
    if (threadIdx.x == 0) outp[0] = sm[0] / (float)NN;
}

// ---------------- host orchestration ----------------
extern "C" void kernel_launch(void* const* d_in, const int* in_sizes, int n_in,
                              void* d_out, int out_size) {
    (void)in_sizes; (void)n_in; (void)out_size;
    const float* x1 = (const float*)d_in[0];
    const float* x2 = (const float*)d_in[1];
    const int* ei1 = (const int*)d_in[2];
    const int* ei2 = (const int*)d_in[3];
    const float* sp[10]; for (int i = 0; i < 10; i++) sp[i] = (const float*)d_in[4 + i];
    const float* tp[10]; for (int i = 0; i < 10; i++) tp[i] = (const float*)d_in[14 + i];
    const float* pW1 = (const float*)d_in[24];
    const float* pb1 = (const float*)d_in[25];
    const float* pa  = (const float*)d_in[26];
    const float* pW2 = (const float*)d_in[27];
    const float* pb2 = (const float*)d_in[28];
    float* out = (float*)d_out;

    cudaFuncSetAttribute(k_tc_gemm, cudaFuncAttributeMaxDynamicSharedMemorySize, DSMEM_TC);

    float *h0, *h1, *teach0, *teach1, *pred0, *pred1, *q;
    float *dinvB, *wgtB, *psum, *psq, *scale, *shift, *losspart;
    int *cntB, *rpB, *curB, *colB, *incl, *bsum;
    cudaGetSymbolAddress((void**)&h0, g_h0);
    cudaGetSymbolAddress((void**)&h1, g_h1);
    cudaGetSymbolAddress((void**)&teach0, g_teach0);
    cudaGetSymbolAddress((void**)&teach1, g_teach1);
    cudaGetSymbolAddress((void**)&pred0, g_pred0);
    cudaGetSymbolAddress((void**)&pred1, g_pred1);
    cudaGetSymbolAddress((void**)&q, g_q);
    cudaGetSymbolAddress((void**)&cntB, g_cnt);
    cudaGetSymbolAddress((void**)&dinvB, g_dinv);
    cudaGetSymbolAddress((void**)&rpB, g_rowptr);
    cudaGetSymbolAddress((void**)&curB, g_cursor);
    cudaGetSymbolAddress((void**)&colB, g_col);
    cudaGetSymbolAddress((void**)&wgtB, g_wgt);
    cudaGetSymbolAddress((void**)&incl, g_scan_incl);
    cudaGetSymbolAddress((void**)&bsum, g_scan_bsum);
    cudaGetSymbolAddress((void**)&psum, g_psum);
    cudaGetSymbolAddress((void**)&psq, g_psq);
    cudaGetSymbolAddress((void**)&scale, g_scale);
    cudaGetSymbolAddress((void**)&shift, g_shift);
    cudaGetSymbolAddress((void**)&losspart, g_losspart);

    // --- build CSR for both views ---
    for (int v = 0; v < 2; v++) {
        const int* ei = v ? ei2 : ei1;
        int* cnt = cntB + v * NN;
        float* dinv = dinvB + v * NN;
        int* rp = rpB + v * (NN + 1);
        int* cur = curB + v * NN;
        int* col = colB + v * ENN;
        float* wgt = wgtB + v * ENN;
        k_init_cnt<<<NB_BN, 256>>>(cnt);
        k_count<<<(EE + 255) / 256, 256>>>(ei, cnt);
        k_dinv<<<NB_BN, 256>>>(cnt, dinv);
        k_scan_block<<<NB_SCAN, 1024>>>(cnt, incl, bsum);
        k_scan_sums<<<1, 32>>>(bsum);
        k_finalize_rowptr<<<NB_BN, 256>>>(cnt, incl, bsum, rp, cur);
        k_fill<<<(ENN + 255) / 256, 256>>>(ei, dinv, cur, col, wgt);
    }

    auto gemm = [&](const float* A, const float* W, const float* bias, const float* ap,
                    float* Cc, int K, int Mt) {
        k_tc_gemm<<<dim3(GX, Mt / 128), 256, DSMEM_TC>>>(A, W, bias, ap, Cc, NN, K, Mt);
    };

    // --- 4 encoder runs ---
    auto encoder = [&](const float* x, int view, const float* const* P, float* outp) {
        const int* rp = rpB + view * (NN + 1);
        const int* col = colB + view * ENN;
        const float* wgt = wgtB + view * ENN;
        // layer 1
        gemm(x, P[0], nullptr, nullptr, h0, 256, 128);
        k_prop<<<12500, 256>>>(rp, col, wgt, h0, P[1], h1);
        k_bn_stats<<<NB_BN, 256>>>(h1, psum, psq);
        k_bn_fin<<<1, 128>>>(psum, psq, P[2], P[3], scale, shift);
        k_bn_apply<<<12500, 256>>>(h1, scale, shift, P[4], h1);
        // layer 2
        gemm(h1, P[5], nullptr, nullptr, h0, 128, 128);
        k_prop<<<12500, 256>>>(rp, col, wgt, h0, P[6], h1);
        k_bn_stats<<<NB_BN, 256>>>(h1, psum, psq);
        k_bn_fin<<<1, 128>>>(psum, psq, P[7], P[8], scale, shift);
        k_bn_apply<<<12500, 256>>>(h1, scale, shift, P[9], outp);
    };

    encoder(x1, 0, sp, out);
    encoder(x2, 1, sp, out + (size_t)NN * 128);
    encoder(x1, 0, tp, teach0);
    encoder(x2, 1, tp, teach1);

    // --- predictor MLP on both student outputs ---
    gemm(out, pW1, pb1, pa, q, 128, 512);
    gemm(q, pW2, pb2, nullptr, pred0, 512, 128);
    gemm(out + (size_t)NN * 128, pW1, pb1, pa, q, 128, 512);
    gemm(q, pW2, pb2, nullptr, pred1, 512, 128);

    // --- loss ---
    k_loss<<<NB_LOSS, 256>>>((const float4*)pred0, (const float4*)teach1,
                             (const float4*)pred1, (const float4*)teach0, losspart);
    k_loss_fin<<<1, 256>>>(losspart, out + (size_t)2 * NN * 128);
}

// round 6
// speedup vs baseline: 1.3754x; 1.2553x over previous
#include <cuda_runtime.h>
#include <cuda_bf16.h>
#include <math.h>
#include <stdint.h>

#define NN 100000
#define EE 1600000
#define ENN (EE + NN)
#define NB_BN 391      /* ceil(NN/256) */
#define NB_LOSS 12500  /* NN warps / 8 warps-per-block */
#define NB_SCAN 98     /* ceil(NN/1024) */
#define GX 782         /* ceil(NN/128) */

// ---------------- static scratch ----------------
__device__ float g_h0[NN * 128];
__device__ float g_h1[NN * 128];
__device__ float g_teach0[NN * 128];
__device__ float g_teach1[NN * 128];
__device__ float g_pred0[NN * 128];
__device__ float g_pred1[NN * 128];
__device__ float g_q[(size_t)NN * 512];

__device__ __nv_bfloat16 g_wthi[65536];
__device__ __nv_bfloat16 g_wtlo[65536];

__device__ int   g_cnt[2 * NN];
__device__ float g_dinv[2 * NN];
__device__ int   g_rowptr[2 * (NN + 1)];
__device__ int   g_cursor[2 * NN];
__device__ int   g_col[2 * ENN];
__device__ float g_wgt[2 * ENN];
__device__ int   g_scan_incl[NN];
__device__ int   g_scan_bsum[NB_SCAN];

__device__ float g_psum[NB_BN * 128];
__device__ float g_psq[NB_BN * 128];
__device__ float g_scale[128];
__device__ float g_shift[128];
__device__ float g_losspart[NB_LOSS];

// ---------------- bf16 mma helper ----------------
__device__ __forceinline__ void mma_bf16(float* c, const uint32_t* a, const uint32_t* b) {
    asm volatile(
        "mma.sync.aligned.m16n8k16.row.col.f32.bf16.bf16.f32 "
        "{%0,%1,%2,%3},{%4,%5,%6,%7},{%8,%9},{%0,%1,%2,%3};"
        : "+f"(c[0]), "+f"(c[1]), "+f"(c[2]), "+f"(c[3])
        : "r"(a[0]), "r"(a[1]), "r"(a[2]), "r"(a[3]), "r"(b[0]), "r"(b[1]));
}

// ---------------- weight prep: W[K,Mt] fp32 -> Wt_hi/Wt_lo [Mt][K] bf16 ----------------
__global__ void k_prep_w(const float* __restrict__ W, __nv_bfloat16* __restrict__ Wh,
                         __nv_bfloat16* __restrict__ Wl, int K, int Mt) {
    int idx = blockIdx.x * 256 + threadIdx.x;
    if (idx >= K * Mt) return;
    int m = idx / K, k = idx - m * K;
    float v = W[(size_t)k * Mt + m];
    __nv_bfloat16 h = __float2bfloat16(v);
    Wh[idx] = h;
    Wl[idx] = __float2bfloat16(v - __bfloat162float(h));
}

// ---------------- bf16-split tensor GEMM ----------------
// C[n,Mt] = A[n,K] @ W[K,Mt] (+bias, +prelu). CTA 128x128, 8 warps (2m x 4n),
// warp tile 64x32, K chunked by 32 (bf16), hi/lo split, 3-term MMA.
#define KC 32
#define STR 36 /* halfs per smem row */

__global__ __launch_bounds__(256) void k_bf_gemm(
    const float* __restrict__ A, const __nv_bfloat16* __restrict__ Wh,
    const __nv_bfloat16* __restrict__ Wl, const float* __restrict__ bias,
    const float* __restrict__ aprelu, float* __restrict__ C,
    int n, int K, int Mt) {
    __shared__ __nv_bfloat16 smh[4 * 128 * STR];
    __nv_bfloat16* Ah = smh;
    __nv_bfloat16* Al = Ah + 128 * STR;
    __nv_bfloat16* Bh = Al + 128 * STR;
    __nv_bfloat16* Bl = Bh + 128 * STR;

    const int tid = threadIdx.x, lane = tid & 31, wid = tid >> 5;
    const int wm = wid & 1, wn = wid >> 1;
    const int bm = blockIdx.x * 128, bn = blockIdx.y * 128;
    const int lg = lane >> 2, lt = lane & 3;

    float acc[4][4][4];
#pragma unroll
    for (int i = 0; i < 4; i++)
#pragma unroll
        for (int j = 0; j < 4; j++)
#pragma unroll
            for (int k = 0; k < 4; k++) acc[i][j][k] = 0.f;

    const int srow = tid >> 1;          // 0..127
    const int sks = (tid & 1) * 16;     // half of the 32-k chunk

    for (int k0 = 0; k0 < K; k0 += KC) {
        // ---- stage A [128][32] fp32 -> hi/lo bf16 ----
        {
            int gr = bm + srow;
            __nv_bfloat16 hv[16], lv[16];
#pragma unroll
            for (int q = 0; q < 4; q++) {
                float4 v = make_float4(0.f, 0.f, 0.f, 0.f);
                if (gr < n) v = *(const float4*)(A + (size_t)gr * K + k0 + sks + q * 4);
                float vs[4] = {v.x, v.y, v.z, v.w};
#pragma unroll
                for (int e = 0; e < 4; e++) {
                    __nv_bfloat16 h = __float2bfloat16(vs[e]);
                    hv[q * 4 + e] = h;
                    lv[q * 4 + e] = __float2bfloat16(vs[e] - __bfloat162float(h));
                }
            }
            uint2* dh = (uint2*)&Ah[srow * STR + sks];
            uint2* dl = (uint2*)&Al[srow * STR + sks];
#pragma unroll
            for (int q = 0; q < 4; q++) {
                dh[q] = ((uint2*)hv)[q];
                dl[q] = ((uint2*)lv)[q];
            }
        }
        // ---- stage B [128 n][32 k] from Wt hi/lo (already [Mt][K] bf16) ----
        {
            const __nv_bfloat16* sh = Wh + (size_t)(bn + srow) * K + k0 + sks;
            const __nv_bfloat16* sl = Wl + (size_t)(bn + srow) * K + k0 + sks;
            uint2* dh = (uint2*)&Bh[srow * STR + sks];
            uint2* dl = (uint2*)&Bl[srow * STR + sks];
#pragma unroll
            for (int q = 0; q < 4; q++) {
                dh[q] = ((const uint2*)sh)[q];
                dl[q] = ((const uint2*)sl)[q];
            }
        }
        __syncthreads();
#pragma unroll
        for (int kk = 0; kk < KC; kk += 16) {
            uint32_t ah[4][4], al[4][4], bh[4][2], bl[4][2];
            const int kb = kk + lt * 2;
#pragma unroll
            for (int mf = 0; mf < 4; mf++) {
                int r = wm * 64 + mf * 16 + lg;
                ah[mf][0] = *(const uint32_t*)&Ah[r * STR + kb];
                ah[mf][1] = *(const uint32_t*)&Ah[(r + 8) * STR + kb];
                ah[mf][2] = *(const uint32_t*)&Ah[r * STR + kb + 8];
                ah[mf][3] = *(const uint32_t*)&Ah[(r + 8) * STR + kb + 8];
                al[mf][0] = *(const uint32_t*)&Al[r * STR + kb];
                al[mf][1] = *(const uint32_t*)&Al[(r + 8) * STR + kb];
                al[mf][2] = *(const uint32_t*)&Al[r * STR + kb + 8];
                al[mf][3] = *(const uint32_t*)&Al[(r + 8) * STR + kb + 8];
            }
#pragma unroll
            for (int nf = 0; nf < 4; nf++) {
                int c = wn * 32 + nf * 8 + lg;
                bh[nf][0] = *(const uint32_t*)&Bh[c * STR + kb];
                bh[nf][1] = *(const uint32_t*)&Bh[c * STR + kb + 8];
                bl[nf][0] = *(const uint32_t*)&Bl[c * STR + kb];
                bl[nf][1] = *(const uint32_t*)&Bl[c * STR + kb + 8];
            }
#pragma unroll
            for (int mf = 0; mf < 4; mf++)
#pragma unroll
                for (int nf = 0; nf < 4; nf++) {
                    mma_bf16(acc[mf][nf], ah[mf], bh[nf]);
                    mma_bf16(acc[mf][nf], ah[mf], bl[nf]);
                    mma_bf16(acc[mf][nf], al[mf], bh[nf]);
                }
        }
        __syncthreads();
    }

    // epilogue (fragment layout: c0,c1 row lg / c2,c3 row lg+8, cols lt*2,+1)
    float alv = aprelu ? __ldg(aprelu) : 0.f;
#pragma unroll
    for (int mf = 0; mf < 4; mf++) {
        int r0 = bm + wm * 64 + mf * 16 + lg;
#pragma unroll
        for (int nf = 0; nf < 4; nf++) {
            int gc = bn + wn * 32 + nf * 8 + lt * 2;
            float2 v0 = make_float2(acc[mf][nf][0], acc[mf][nf][1]);
            float2 v1 = make_float2(acc[mf][nf][2], acc[mf][nf][3]);
            if (bias) {
                float b0 = __ldg(&bias[gc]), b1 = __ldg(&bias[gc + 1]);
                v0.x += b0; v0.y += b1; v1.x += b0; v1.y += b1;
            }
            if (aprelu) {
                v0.x = v0.x >= 0.f ? v0.x : alv * v0.x;
                v0.y = v0.y >= 0.f ? v0.y : alv * v0.y;
                v1.x = v1.x >= 0.f ? v1.x : alv * v1.x;
                v1.y = v1.y >= 0.f ? v1.y : alv * v1.y;
            }
            if (r0 < n) *(float2*)(C + (size_t)r0 * Mt + gc) = v0;
            if (r0 + 8 < n) *(float2*)(C + (size_t)(r0 + 8) * Mt + gc) = v1;
        }
    }
}

// ---------------- CSR build ----------------
__global__ void k_init_cnt(int* cnt) {
    int i = blockIdx.x * 256 + threadIdx.x;
    if (i < NN) cnt[i] = 1;
}
__global__ void k_count(const int* __restrict__ ei, int* cnt) {
    int e = blockIdx.x * 256 + threadIdx.x;
    if (e < EE) atomicAdd(&cnt[ei[EE + e]], 1);
}
__global__ void k_dinv(const int* __restrict__ cnt, float* dinv) {
    int i = blockIdx.x * 256 + threadIdx.x;
    if (i < NN) dinv[i] = rsqrtf((float)cnt[i]);
}
__global__ void k_scan_block(const int* __restrict__ cnt, int* incl, int* bsum) {
    __shared__ int sm[1024];
    int i = blockIdx.x * 1024 + threadIdx.x;
    int v = (i < NN) ? cnt[i] : 0;
    sm[threadIdx.x] = v;
    __syncthreads();
    for (int off = 1; off < 1024; off <<= 1) {
        int t = (threadIdx.x >= off) ? sm[threadIdx.x - off] : 0;
        __syncthreads();
        sm[threadIdx.x] += t;
        __syncthreads();
    }
    if (i < NN) incl[i] = sm[threadIdx.x];
    if (threadIdx.x == 1023) bsum[blockIdx.x] = sm[1023];
}
__global__ void k_scan_sums(int* bsum) {
    if (threadIdx.x == 0 && blockIdx.x == 0) {
        int acc = 0;
        for (int b = 0; b < NB_SCAN; b++) { int t = bsum[b]; bsum[b] = acc; acc += t; }
    }
}
__global__ void k_finalize_rowptr(const int* __restrict__ cnt, const int* __restrict__ incl,
                                  const int* __restrict__ bsum, int* rowptr, int* cursor) {
    int i = blockIdx.x * 256 + threadIdx.x;
    if (i < NN) {
        int inclg = incl[i] + bsum[i >> 10];
        int excl = inclg - cnt[i];
        rowptr[i] = excl;
        cursor[i] = excl;
        if (i == NN - 1) rowptr[NN] = inclg;
    }
}
__global__ void k_fill(const int* __restrict__ ei, const float* __restrict__ dinv,
                       int* cursor, int* col, float* wgt) {
    int t = blockIdx.x * 256 + threadIdx.x;
    if (t < EE) {
        int s = ei[t], d = ei[EE + t];
        int p = atomicAdd(&cursor[d], 1);
        col[p] = s;
        wgt[p] = dinv[s] * dinv[d];
    } else if (t < ENN) {
        int i = t - EE;
        int p = atomicAdd(&cursor[i], 1);
        col[p] = i;
        wgt[p] = dinv[i] * dinv[i];
    }
}

// ---------------- propagate ----------------
__global__ __launch_bounds__(256) void k_prop(const int* __restrict__ rowptr,
                                              const int* __restrict__ col,
                                              const float* __restrict__ wgt,
                                              const float* __restrict__ h,
                                              const float* __restrict__ bias,
                                              float* __restrict__ out) {
    int w = (blockIdx.x * 256 + threadIdx.x) >> 5;
    int lane = threadIdx.x & 31;
    if (w >= NN) return;
    int beg = rowptr[w], end = rowptr[w + 1];
    float4 acc = make_float4(0.f, 0.f, 0.f, 0.f);
    const float4* H = (const float4*)h;
    for (int e = beg; e < end; e++) {
        int s = __ldg(&col[e]);
        float wv = __ldg(&wgt[e]);
        float4 v = __ldg(&H[(size_t)s * 32 + lane]);
        acc.x = fmaf(wv, v.x, acc.x);
        acc.y = fmaf(wv, v.y, acc.y);
        acc.z = fmaf(wv, v.z, acc.z);
        acc.w = fmaf(wv, v.w, acc.w);
    }
    float4 b = ((const float4*)bias)[lane];
    acc.x += b.x; acc.y += b.y; acc.z += b.z; acc.w += b.w;
    ((float4*)out)[(size_t)w * 32 + lane] = acc;
}

// ---------------- BN ----------------
__global__ __launch_bounds__(256) void k_bn_stats(const float* __restrict__ x,
                                                  float* __restrict__ psum,
                                                  float* __restrict__ psq) {
    __shared__ float4 smS[256], smQ[256];
    int t = threadIdx.x;
    int cg = t & 31, rr = t >> 5;
    int rowStart = blockIdx.x * 256;
    int rowEnd = rowStart + 256; if (rowEnd > NN) rowEnd = NN;
    float4 s = make_float4(0.f, 0.f, 0.f, 0.f), q = s;
    const float4* X = (const float4*)x;
    for (int r = rowStart + rr; r < rowEnd; r += 8) {
        float4 v = X[(size_t)r * 32 + cg];
        s.x += v.x; s.y += v.y; s.z += v.z; s.w += v.w;
        q.x = fmaf(v.x, v.x, q.x); q.y = fmaf(v.y, v.y, q.y);
        q.z = fmaf(v.z, v.z, q.z); q.w = fmaf(v.w, v.w, q.w);
    }
    smS[t] = s; smQ[t] = q;
    __syncthreads();
    if (rr == 0) {
        for (int k = 1; k < 8; k++) {
            float4 a = smS[k * 32 + cg], b = smQ[k * 32 + cg];
            s.x += a.x; s.y += a.y; s.z += a.z; s.w += a.w;
            q.x += b.x; q.y += b.y; q.z += b.z; q.w += b.w;
        }
        ((float4*)psum)[blockIdx.x * 32 + cg] = s;
        ((float4*)psq)[blockIdx.x * 32 + cg] = q;
    }
}
__global__ void k_bn_fin(const float* __restrict__ psum, const float* __restrict__ psq,
                         const float* __restrict__ g, const float* __restrict__ be,
                         float* scale, float* shift) {
    int c = threadIdx.x;
    float s = 0.f, q = 0.f;
    for (int b = 0; b < NB_BN; b++) { s += psum[b * 128 + c]; q += psq[b * 128 + c]; }
    float mu = s / (float)NN;
    float var = q / (float)NN - mu * mu;
    var = fmaxf(var, 0.f);
    float inv = rsqrtf(var + 1e-5f);
    float sc = g[c] * inv;
    scale[c] = sc;
    shift[c] = be[c] - mu * sc;
}
__global__ __launch_bounds__(256) void k_bn_apply(const float* __restrict__ x,
                                                  const float* __restrict__ scale,
                                                  const float* __restrict__ shift,
                                                  const float* __restrict__ aptr,
                                                  float* __restrict__ out) {
    int i = blockIdx.x * 256 + threadIdx.x;
    if (i >= NN * 32) return;
    int cg = i & 31;
    float a = *aptr;
    float4 v = ((const float4*)x)[i];
    float4 sc = ((const float4*)scale)[cg];
    float4 sh = ((const float4*)shift)[cg];
    v.x = fmaf(v.x, sc.x, sh.x); v.y = fmaf(v.y, sc.y, sh.y);
    v.z = fmaf(v.z, sc.z, sh.z); v.w = fmaf(v.w, sc.w, sh.w);
    v.x = v.x >= 0.f ? v.x : a * v.x;
    v.y = v.y >= 0.f ? v.y : a * v.y;
    v.z = v.z >= 0.f ? v.z : a * v.z;
    v.w = v.w >= 0.f ? v.w : a * v.w;
    ((float4*)out)[i] = v;
}

// ---------------- loss ----------------
__global__ __launch_bounds__(256) void k_loss(const float4* __restrict__ p1,
                                              const float4* __restrict__ t2,
                                              const float4* __restrict__ p2,
                                              const float4* __restrict__ t1,
                                              float* __restrict__ part) {
    int w = (blockIdx.x * 256 + threadIdx.x) >> 5;
    int lane = threadIdx.x & 31;
    float contrib = 0.f;
    if (w < NN) {
        float4 a = p1[(size_t)w * 32 + lane];
        float4 b = t2[(size_t)w * 32 + lane];
        float4 c = p2[(size_t)w * 32 + lane];
        float4 d = t1[(size_t)w * 32 + lane];
        float dab = a.x * b.x + a.y * b.y + a.z * b.z + a.w * b.w;
        float naa = a.x * a.x + a.y * a.y + a.z * a.z + a.w * a.w;
        float nbb = b.x * b.x + b.y * b.y + b.z * b.z + b.w * b.w;
        float dcd = c.x * d.x + c.y * d.y + c.z * d.z + c.w * d.w;
        float ncc = c.x * c.x + c.y * c.y + c.z * c.z + c.w * c.w;
        float ndd = d.x * d.x + d.y * d.y + d.z * d.z + d.w * d.w;
        for (int off = 16; off; off >>= 1) {
            dab += __shfl_xor_sync(0xffffffffu, dab, off);
            naa += __shfl_xor_sync(0xffffffffu, naa, off);
            nbb += __shfl_xor_sync(0xffffffffu, nbb, off);
            dcd += __shfl_xor_sync(0xffffffffu, dcd, off);
            ncc += __shfl_xor_sync(0xffffffffu, ncc, off);
            ndd += __shfl_xor_sync(0xffffffffu, ndd, off);
        }
        if (lane == 0) {
            float c1 = dab / (fmaxf(sqrtf(naa), 1e-12f) * fmaxf(sqrtf(nbb), 1e-12f));
            float c2 = dcd / (fmaxf(sqrtf(ncc), 1e-12f) * fmaxf(sqrtf(ndd), 1e-12f));
            contrib = 4.f - 2.f * c1 - 2.f * c2;
        }
    }
    __shared__ float sm[8];
    int wl = threadIdx.x >> 5;
    if (lane == 0) sm[wl] = contrib;
    __syncthreads();
    if (threadIdx.x == 0) {
        float s = 0.f;
        for (int i = 0; i < 8; i++) s += sm[i];
        part[blockIdx.x] = s;
    }
}
__global__ void k_loss_fin(const float* __restrict__ part, float* __restrict__ outp) {
    __shared__ float sm[256];
    float s = 0.f;
    for (int i = threadIdx.x; i < NB_LOSS; i += 256) s += part[i];
    sm[threadIdx.x] = s;
    __syncthreads();
    for (int off = 128; off; off >>= 1) {
        if (threadIdx.x < off) sm[threadIdx.x] += sm[threadIdx.x + off];
        __syncthreads();
    }
    if (threadIdx.x == 0) outp[0] = sm[0] / (float)NN;
}

// ---------------- host orchestration ----------------
extern "C" void kernel_launch(void* const* d_in, const int* in_sizes, int n_in,
                              void* d_out, int out_size) {
    (void)in_sizes; (void)n_in; (void)out_size;
    const float* x1 = (const float*)d_in[0];
    const float* x2 = (const float*)d_in[1];
    const int* ei1 = (const int*)d_in[2];
    const int* ei2 = (const int*)d_in[3];
    const float* sp[10]; for (int i = 0; i < 10; i++) sp[i] = (const float*)d_in[4 + i];
    const float* tp[10]; for (int i = 0; i < 10; i++) tp[i] = (const float*)d_in[14 + i];
    const float* pW1 = (const float*)d_in[24];
    const float* pb1 = (const float*)d_in[25];
    const float* pa  = (const float*)d_in[26];
    const float* pW2 = (const float*)d_in[27];
    const float* pb2 = (const float*)d_in[28];
    float* out = (float*)d_out;

    float *h0, *h1, *teach0, *teach1, *pred0, *pred1, *q;
    float *dinvB, *wgtB, *psum, *psq, *scale, *shift, *losspart;
    __nv_bfloat16 *wthi, *wtlo;
    int *cntB, *rpB, *curB, *colB, *incl, *bsum;
    cudaGetSymbolAddress((void**)&h0, g_h0);
    cudaGetSymbolAddress((void**)&h1, g_h1);
    cudaGetSymbolAddress((void**)&teach0, g_teach0);
    cudaGetSymbolAddress((void**)&teach1, g_teach1);
    cudaGetSymbolAddress((void**)&pred0, g_pred0);
    cudaGetSymbolAddress((void**)&pred1, g_pred1);
    cudaGetSymbolAddress((void**)&q, g_q);
    cudaGetSymbolAddress((void**)&wthi, g_wthi);
    cudaGetSymbolAddress((void**)&wtlo, g_wtlo);
    cudaGetSymbolAddress((void**)&cntB, g_cnt);
    cudaGetSymbolAddress((void**)&dinvB, g_dinv);
    cudaGetSymbolAddress((void**)&rpB, g_rowptr);
    cudaGetSymbolAddress((void**)&curB, g_cursor);
    cudaGetSymbolAddress((void**)&colB, g_col);
    cudaGetSymbolAddress((void**)&wgtB, g_wgt);
    cudaGetSymbolAddress((void**)&incl, g_scan_incl);
    cudaGetSymbolAddress((void**)&bsum, g_scan_bsum);
    cudaGetSymbolAddress((void**)&psum, g_psum);
    cudaGetSymbolAddress((void**)&psq, g_psq);
    cudaGetSymbolAddress((void**)&scale, g_scale);
    cudaGetSymbolAddress((void**)&shift, g_shift);
    cudaGetSymbolAddress((void**)&losspart, g_losspart);

    // --- build CSR for both views ---
    for (int v = 0; v < 2; v++) {
        const int* ei = v ? ei2 : ei1;
        int* cnt = cntB + v * NN;
        float* dinv = dinvB + v * NN;
        int* rp = rpB + v * (NN + 1);
        int* cur = curB + v * NN;
        int* col = colB + v * ENN;
        float* wgt = wgtB + v * ENN;
        k_init_cnt<<<NB_BN, 256>>>(cnt);
        k_count<<<(EE + 255) / 256, 256>>>(ei, cnt);
        k_dinv<<<NB_BN, 256>>>(cnt, dinv);
        k_scan_block<<<NB_SCAN, 1024>>>(cnt, incl, bsum);
        k_scan_sums<<<1, 32>>>(bsum);
        k_finalize_rowptr<<<NB_BN, 256>>>(cnt, incl, bsum, rp, cur);
        k_fill<<<(ENN + 255) / 256, 256>>>(ei, dinv, cur, col, wgt);
    }

    auto gemm = [&](const float* A, const float* W, const float* bias, const float* ap,
                    float* Cc, int K, int Mt) {
        k_prep_w<<<(K * Mt + 255) / 256, 256>>>(W, wthi, wtlo, K, Mt);
        k_bf_gemm<<<dim3(GX, Mt / 128), 256>>>(A, wthi, wtlo, bias, ap, Cc, NN, K, Mt);
    };

    // --- 4 encoder runs ---
    auto encoder = [&](const float* x, int view, const float* const* P, float* outp) {
        const int* rp = rpB + view * (NN + 1);
        const int* col = colB + view * ENN;
        const float* wgt = wgtB + view * ENN;
        // layer 1
        gemm(x, P[0], nullptr, nullptr, h0, 256, 128);
        k_prop<<<12500, 256>>>(rp, col, wgt, h0, P[1], h1);
        k_bn_stats<<<NB_BN, 256>>>(h1, psum, psq);
        k_bn_fin<<<1, 128>>>(psum, psq, P[2], P[3], scale, shift);
        k_bn_apply<<<12500, 256>>>(h1, scale, shift, P[4], h1);
        // layer 2
        gemm(h1, P[5], nullptr, nullptr, h0, 128, 128);
        k_prop<<<12500, 256>>>(rp, col, wgt, h0, P[6], h1);
        k_bn_stats<<<NB_BN, 256>>>(h1, psum, psq);
        k_bn_fin<<<1, 128>>>(psum, psq, P[7], P[8], scale, shift);
        k_bn_apply<<<12500, 256>>>(h1, scale, shift, P[9], outp);
    };

    encoder(x1, 0, sp, out);
    encoder(x2, 1, sp, out + (size_t)NN * 128);
    encoder(x1, 0, tp, teach0);
    encoder(x2, 1, tp, teach1);

    // --- predictor MLP on both student outputs ---
    gemm(out, pW1, pb1, pa, q, 128, 512);
    gemm(q, pW2, pb2, nullptr, pred0, 512, 128);
    gemm(out + (size_t)NN * 128, pW1, pb1, pa, q, 128, 512);
    gemm(q, pW2, pb2, nullptr, pred1, 512, 128);

    // --- loss ---
    k_loss<<<NB_LOSS, 256>>>((const float4*)pred0, (const float4*)teach1,
                             (const float4*)pred1, (const float4*)teach0, losspart);
    k_loss_fin<<<1, 256>>>(losspart, out + (size_t)2 * NN * 128);
}